// round 1
// baseline (speedup 1.0000x reference)
#include <cuda_runtime.h>
#include <cstdint>

// AFM fused kernel, fp32 CUDA-core baseline.
// One CTA per batch element. B=1024, F=33 (P=528 pairs), D=A=128.
//
// out[b] = concat(gnn[b],  100 * softmax_p( gnn[b] . relu(W @ (x_i*x_j) + bias) ) weighted sum of (x_i*x_j))

#define F_   33
#define D_   128
#define A_   128
#define P_   528          // F*(F-1)/2
#define THREADS_ 256
#define MTILE 64
#define NTILES 9          // ceil(528/64)

struct Smem {
    float xs[F_][132];       // x[b], padded rows (132 floats keeps float4 alignment, staggers banks)
    float Ws[D_][132];       // W transposed: Ws[k][a]
    float Is[D_][68];        // inner tile, k-major: Is[k][m]  (68 = 64 + pad, 16B-aligned rows)
    float scores[P_];
    float red[16];
    unsigned short pairs[P_]; // (i<<8)|j
};

__global__ void __launch_bounds__(THREADS_, 1)
afm_kernel(const float* __restrict__ gnn,
           const float* __restrict__ x,
           const float* __restrict__ W,
           const float* __restrict__ bias,
           float* __restrict__ out)
{
    extern __shared__ unsigned char smem_raw[];
    Smem* s = reinterpret_cast<Smem*>(smem_raw);

    const int b    = blockIdx.x;
    const int tid  = threadIdx.x;
    const int lane = tid & 31;
    const int wid  = tid >> 5;
    const int tm   = tid & 15;     // 16 m-quads -> 64 m rows
    const int tn   = tid >> 4;     // 16 a-octets -> 128 a cols

    // ---- build pair table (row-major triu, k=1) ----
    for (int p = tid; p < P_; p += THREADS_) {
        int i = 0, base = 0;
        while (base + (F_ - 1 - i) <= p) { base += F_ - 1 - i; ++i; }
        int j = i + 1 + (p - base);
        s->pairs[p] = (unsigned short)((i << 8) | j);
    }
    for (int p = tid; p < P_; p += THREADS_) s->scores[p] = 0.f;

    // ---- load x[b] into smem (float4, coalesced) ----
    const float4* xb = reinterpret_cast<const float4*>(x + (size_t)b * F_ * D_);
    for (int e = tid; e < F_ * D_ / 4; e += THREADS_) {
        int f = e >> 5;      // 32 float4 per 128-float row
        int q = e & 31;
        *reinterpret_cast<float4*>(&s->xs[f][q * 4]) = xb[e];
    }
    // ---- load W transposed into smem: Ws[k][a] = W[a*128 + k] ----
    for (int e = tid; e < D_ * A_; e += THREADS_) {
        int a = e >> 7, k = e & 127;
        s->Ws[k][a] = W[e];
    }
    __syncthreads();

    // per-thread a-range (8 a's) register data
    const int a0 = tn * 8;
    float greg[8], breg[8];
#pragma unroll
    for (int n = 0; n < 8; ++n) {
        greg[n] = gnn[(size_t)b * A_ + a0 + n];
        breg[n] = bias[a0 + n];
    }

    // ==== main loop over M-tiles of pairs ====
    for (int t = 0; t < NTILES; ++t) {
        const int m0 = t * MTILE;
        __syncthreads();   // previous tile's Is reads complete

        // fill Is[k][m] = xs[i][k]*xs[j][k] for m in [m0, m0+64); consecutive
        // threads take consecutive k -> conflict-free xs reads.
        for (int e = tid; e < D_ * (MTILE / 4); e += THREADS_) {
            int k  = e & 127;
            int mq = e >> 7;
            float4 v;
#pragma unroll
            for (int q = 0; q < 4; ++q) {
                int m = m0 + mq * 4 + q;
                float val = 0.f;
                if (m < P_) {
                    unsigned short pr = s->pairs[m];
                    val = s->xs[pr >> 8][k] * s->xs[pr & 255][k];
                }
                reinterpret_cast<float*>(&v)[q] = val;
            }
            *reinterpret_cast<float4*>(&s->Is[k][mq * 4]) = v;
        }
        __syncthreads();

        // register-tiled GEMM: acc[4 m][8 a]
        float acc[4][8];
#pragma unroll
        for (int mi = 0; mi < 4; ++mi)
#pragma unroll
            for (int ni = 0; ni < 8; ++ni) acc[mi][ni] = 0.f;

#pragma unroll 4
        for (int k = 0; k < D_; ++k) {
            float4 iv = *reinterpret_cast<const float4*>(&s->Is[k][tm * 4]);
            float4 w0 = *reinterpret_cast<const float4*>(&s->Ws[k][a0]);
            float4 w1 = *reinterpret_cast<const float4*>(&s->Ws[k][a0 + 4]);
            float im[4] = {iv.x, iv.y, iv.z, iv.w};
            float wv[8] = {w0.x, w0.y, w0.z, w0.w, w1.x, w1.y, w1.z, w1.w};
#pragma unroll
            for (int mi = 0; mi < 4; ++mi)
#pragma unroll
                for (int ni = 0; ni < 8; ++ni)
                    acc[mi][ni] = fmaf(im[mi], wv[ni], acc[mi][ni]);
        }

        // epilogue: bias + relu + dot with gnn -> partial scores
#pragma unroll
        for (int mi = 0; mi < 4; ++mi) {
            int m = m0 + tm * 4 + mi;
            float sc = 0.f;
            if (m < P_) {
#pragma unroll
                for (int n = 0; n < 8; ++n) {
                    float z = fmaxf(acc[mi][n] + breg[n], 0.f);
                    sc = fmaf(greg[n], z, sc);
                }
            }
            sc += __shfl_xor_sync(0xffffffffu, sc, 16);   // fold the 2 tn's in this warp
            if (lane < 16 && m < P_) atomicAdd(&s->scores[m], sc);
        }
    }
    __syncthreads();

    // ==== softmax over scores[528] ====
    float lmax = -1e30f;
    for (int p = tid; p < P_; p += THREADS_) lmax = fmaxf(lmax, s->scores[p]);
#pragma unroll
    for (int o = 16; o; o >>= 1) lmax = fmaxf(lmax, __shfl_xor_sync(0xffffffffu, lmax, o));
    if (lane == 0) s->red[wid] = lmax;
    __syncthreads();
    if (tid < 32) {
        float v = (tid < 8) ? s->red[tid] : -1e30f;
#pragma unroll
        for (int o = 4; o; o >>= 1) v = fmaxf(v, __shfl_xor_sync(0xffffffffu, v, o));
        if (tid == 0) s->red[8] = v;
    }
    __syncthreads();
    const float mx = s->red[8];

    float lsum = 0.f;
    for (int p = tid; p < P_; p += THREADS_) {
        float e = expf(s->scores[p] - mx);
        s->scores[p] = e;
        lsum += e;
    }
#pragma unroll
    for (int o = 16; o; o >>= 1) lsum += __shfl_xor_sync(0xffffffffu, lsum, o);
    if (lane == 0) s->red[wid] = lsum;
    __syncthreads();
    if (tid < 32) {
        float v = (tid < 8) ? s->red[tid] : 0.f;
#pragma unroll
        for (int o = 4; o; o >>= 1) v += __shfl_xor_sync(0xffffffffu, v, o);
        if (tid == 0) s->red[9] = v;
    }
    __syncthreads();
    const float scale = 100.f / s->red[9];

    // ==== attn_output[d] = scale * sum_p exp_p * xs[i][d]*xs[j][d] ====
    const int d    = tid & 127;
    const int half = tid >> 7;
    float accd = 0.f;
    const int pstart = half * (P_ / 2);
    for (int p = pstart; p < pstart + P_ / 2; ++p) {
        unsigned short pr = s->pairs[p];
        accd = fmaf(s->scores[p], s->xs[pr >> 8][d] * s->xs[pr & 255][d], accd);
    }
    float* part = reinterpret_cast<float*>(s->Is);   // reuse Is as [2][128] partial buffer
    part[half * 128 + d] = accd;
    __syncthreads();

    float* outb = out + (size_t)b * (A_ + D_);
    if (tid < 128) {
        outb[tid]       = gnn[(size_t)b * A_ + tid];
        outb[128 + tid] = (part[tid] + part[128 + tid]) * scale;
    }
}

extern "C" void kernel_launch(void* const* d_in, const int* in_sizes, int n_in,
                              void* d_out, int out_size)
{
    const float* gnn  = (const float*)d_in[0];   // [B, 128]
    const float* x    = (const float*)d_in[1];   // [B, 33, 128]
    const float* W    = (const float*)d_in[2];   // [128, 128]
    const float* bias = (const float*)d_in[3];   // [128]
    float* out        = (float*)d_out;           // [B, 256]

    const int B = in_sizes[0] / A_;

    cudaFuncSetAttribute(afm_kernel, cudaFuncAttributeMaxDynamicSharedMemorySize,
                         (int)sizeof(Smem));
    afm_kernel<<<B, THREADS_, sizeof(Smem)>>>(gnn, x, W, bias, out);
}